// round 8
// baseline (speedup 1.0000x reference)
#include <cuda_runtime.h>
#include <cuda_bf16.h>
#include <cstdint>

#define N_SERIES 2048
#define N_TIME   4096
#define INPUT_SIZE 28
#define OUTPUT_SIZE 7
#define SEAS 7
#define EMB  9
#define S_LEN (N_TIME + SEAS)   /* 4103 */

#define OFF_YHAT 0
#define OFF_YWIN 401408
#define OFF_LEV  501760
#define OFF_SEAS (501760 + N_SERIES * N_TIME)

/* 39 relay chunks x 105 steps body, WARM=455 warmup (65 periods -> per-link
   and per-fine-state non-gauge error ~1.3e-5 by the measured 0.857/period
   contraction). Gauge (scale) mode removed exactly by the chain fixup.
   Fine states recorded every 35 steps during the body -> 117 fine chunks
   for the store pass. */
#define NCH1 39
#define BODY1 105
#define WARM 455
#define TS   35
#define NCH2 117
#define ROWW 44    /* smem row stride (floats); 176B, 16B-aligned for cp.async */

__device__ float g_flev  [NCH2][N_SERIES];
__device__ float g_fring [NCH2][SEAS][N_SERIES];
__device__ float g_endlev[NCH1][N_SERIES];
__device__ float g_gam   [NCH2][N_SERIES];

__device__ __forceinline__ float frcp(float x) {
    float r;
    asm("rcp.approx.f32 %0, %1;" : "=f"(r) : "f"(x));
    return r;
}

__device__ __forceinline__ uint32_t s2u(const void* p) {
    uint32_t a;
    asm("{ .reg .u64 t; cvta.to.shared.u64 t, %1; cvt.u32.u64 %0, t; }"
        : "=r"(a) : "l"(p));
    return a;
}
__device__ __forceinline__ void cp16(uint32_t d, const void* g) {
    asm volatile("cp.async.ca.shared.global [%0], [%1], 16;" :: "r"(d), "l"(g));
}
#define CP_COMMIT() asm volatile("cp.async.commit_group;" ::: "memory")
#define CP_WAIT0()  asm volatile("cp.async.wait_group 0;" ::: "memory")
#define CP_WAIT1()  asm volatile("cp.async.wait_group 1;" ::: "memory")

__device__ __forceinline__ void load_params(const int* idxs, const float* emb,
                                            int s, float& a, float& oma,
                                            float& b, float& omb, float* is)
{
    const float* ew = emb + (size_t)idxs[s] * EMB;
    a = 1.0f / (1.0f + __expf(-ew[0]));
    b = 1.0f / (1.0f + __expf(-ew[1]));
    oma = 1.0f - a;
    omb = 1.0f - b;
#pragma unroll
    for (int k = 0; k < SEAS; k++) is[k] = __expf(ew[2 + k]);
}

/* ============ Pass A: dual-series threads, 64-row tiles ============ */

/* cooperative cp.async of [64 rows] x [40 floats]: 640 16B chunks */
__device__ __forceinline__ void tile_cp64(uint32_t sdst, const float* gsrc,
                                          int lane, bool ovr)
{
#pragma unroll
    for (int p = 0; p < 20; p++) {
        int k = p * 32 + lane;
        int r = k / 10;
        int q = k - r * 10;
        if (!(ovr && q == 9))
            cp16(sdst + (uint32_t)(r * ROWW + q * 4) * 4,
                 gsrc + (r << 12) + (q << 2));
    }
}

/* state-only period-batched scan of a 35-step tile for TWO series.
   aq[j] = a * (1/ring[j]) is carried instead of qring (shorter ax path). */
__device__ __forceinline__ void scan2(const float* row0, const float* row1,
                                      float a0, float oma0, float b0, float omb0,
                                      float a1, float oma1, float b1, float omb1,
                                      float& lev0, float& lev1,
                                      float* ring0, float* ring1,
                                      float* aq0, float* aq1)
{
#pragma unroll
    for (int g = 0; g < TS / SEAS; g++) {
        float yt0[SEAS], yt1[SEAS], ax0[SEAS], ax1[SEAS];
#pragma unroll
        for (int j = 0; j < SEAS; j++) {
            yt0[j] = row0[g * SEAS + j];
            yt1[j] = row1[g * SEAS + j];
        }
#pragma unroll
        for (int j = 0; j < SEAS; j++) {
            ax0[j] = yt0[j] * aq0[j];
            ax1[j] = yt1[j] * aq1[j];
        }
#pragma unroll
        for (int j = 0; j < SEAS; j++) {
            lev0 = fmaf(oma0, lev0, ax0[j]);
            lev1 = fmaf(oma1, lev1, ax1[j]);
            float ns0 = fmaf(omb0, ring0[j], (b0 * yt0[j]) * frcp(lev0));
            float ns1 = fmaf(omb1, ring1[j], (b1 * yt1[j]) * frcp(lev1));
            ring0[j] = ns0;  aq0[j] = a0 * frcp(ns0);
            ring1[j] = ns1;  aq1[j] = a1 * frcp(ns1);
        }
    }
}

__global__ void __launch_bounds__(32, 1)
passA_kernel(const float* __restrict__ y, const int* __restrict__ idxs,
             const float* __restrict__ emb)
{
    __shared__ __align__(16) float ty[2][64][ROWW];
    const int c    = blockIdx.x >> 5;        /* chunk 0..38 */
    const int sg   = blockIdx.x & 31;        /* 64-series group */
    const int lane = threadIdx.x;
    const int s0   = sg * 64 + lane;
    const int s1   = s0 + 32;

    float a0, oma0, b0, omb0, is0[SEAS];
    float a1, oma1, b1, omb1, is1[SEAS];
    load_params(idxs, emb, s0, a0, oma0, b0, omb0, is0);
    load_params(idxs, emb, s1, a1, oma1, b1, omb1, is1);

    const int tc = c * BODY1 + 1;
    int t0 = tc - WARM;
    if (t0 < 1) t0 = 1;
    const int wtiles = (tc - t0) / TS;
    const int ntiles = wtiles + 3;

    float lev0 = __fdividef(__ldg(y + (size_t)s0 * N_TIME + (t0 - 1)), is0[0]);
    float lev1 = __fdividef(__ldg(y + (size_t)s1 * N_TIME + (t0 - 1)), is1[0]);
    float ring0[SEAS] = { is0[1], is0[2], is0[3], is0[4], is0[5], is0[6], is0[0] };
    float ring1[SEAS] = { is1[1], is1[2], is1[3], is1[4], is1[5], is1[6], is1[0] };
    float aq0[SEAS], aq1[SEAS];
#pragma unroll
    for (int j = 0; j < SEAS; j++) {
        aq0[j] = a0 * frcp(ring0[j]);
        aq1[j] = a1 * frcp(ring1[j]);
    }

    const float* ygrp = y + (size_t)(sg * 64) * N_TIME;
    const uint32_t tyb0 = s2u(&ty[0][0][0]);
    const uint32_t tyb1 = s2u(&ty[1][0][0]);

    {   /* prefetch tile 0 */
        int w0 = t0 & ~3;
        tile_cp64(tyb0, ygrp + w0, lane, (w0 + 40 > N_TIME));
        CP_COMMIT();
    }

    int tstart = t0;
#pragma unroll 1
    for (int tile = 0; tile < ntiles; tile++) {
        const int buf = tile & 1;
        if (tile + 1 < ntiles) {
            int w0 = (tstart + TS) & ~3;
            tile_cp64(buf ? tyb0 : tyb1, ygrp + w0, lane, (w0 + 40 > N_TIME));
            CP_COMMIT();
            CP_WAIT1();
        } else {
            CP_WAIT0();
        }
        __syncwarp();

        if (tile >= wtiles) {
            const int m = 3 * c + (tile - wtiles);
            g_flev[m][s0] = lev0;
            g_flev[m][s1] = lev1;
#pragma unroll
            for (int j = 0; j < SEAS; j++) {
                g_fring[m][j][s0] = ring0[j];
                g_fring[m][j][s1] = ring1[j];
            }
        }

        const int d = tstart & 3;
        const float* row0 = &ty[buf][lane][0] + d;
        const float* row1 = &ty[buf][lane + 32][0] + d;
        scan2(row0, row1, a0, oma0, b0, omb0, a1, oma1, b1, omb1,
              lev0, lev1, ring0, ring1, aq0, aq1);
        __syncwarp();
        tstart += TS;
    }
    g_endlev[c][s0] = lev0;
    g_endlev[c][s1] = lev1;
}

/* ---- gauge chain: lambda_c = lambda_{c-1} * flev[3c]/endlev[c-1] ---- */
__global__ void fixup_kernel()
{
    int s = blockIdx.x * blockDim.x + threadIdx.x;
    if (s >= N_SERIES) return;
    float kap = 1.0f;
#pragma unroll
    for (int c = 0; c < NCH1; c++) {
        if (c >= 5)
            kap *= __fdividef(g_flev[3 * c][s], g_endlev[c - 1][s]);
        g_gam[3 * c][s]     = kap;
        g_gam[3 * c + 1][s] = kap;
        g_gam[3 * c + 2][s] = kap;
    }
}

/* ============ Pass C: 117 fine chunks x 35 steps, stores L,S ============ */

__device__ __forceinline__ void tile_cp32(uint32_t sdst, const float* gsrc,
                                          int lane, bool ovr)
{
#pragma unroll
    for (int p = 0; p < 10; p++) {
        int k = p * 32 + lane;
        int r = k / 10;
        int q = k - r * 10;
        if (!(ovr && q == 9))
            cp16(sdst + (uint32_t)(r * ROWW + q * 4) * 4,
                 gsrc + (r << 12) + (q << 2));
    }
}

__global__ void __launch_bounds__(32)
passC_kernel(const float* __restrict__ y, const int* __restrict__ idxs,
             const float* __restrict__ emb,
             float* __restrict__ L, float* __restrict__ S)
{
    __shared__ __align__(16) float ty[32][ROWW];   /* y tile -> L tile */
    __shared__ float ts[32][37];
    const int m    = blockIdx.x / 64;
    const int sg   = blockIdx.x % 64;
    const int lane = threadIdx.x;
    const int s    = sg * 32 + lane;

    const int tstart = m * TS + 1;
    const int d  = tstart & 3;
    const int w0 = tstart - d;

    const float* ygrp = y + (size_t)(sg * 32) * N_TIME;
    tile_cp32(s2u(&ty[0][0]), ygrp + w0, lane, (w0 + 40 > N_TIME));
    CP_COMMIT();

    float a, oma, b, omb, is[SEAS];
    load_params(idxs, emb, s, a, oma, b, omb, is);

    const float gam  = g_gam[m][s];
    const float igam = frcp(gam);
    float lev = g_flev[m][s] * igam;
    float ring[SEAS], aq[SEAS];
#pragma unroll
    for (int j = 0; j < SEAS; j++) {
        ring[j] = g_fring[m][j][s] * gam;
        aq[j]   = a * frcp(ring[j]);
    }

    if (m == 0) {
        float* Sr = S + (size_t)s * S_LEN;
#pragma unroll
        for (int k = 0; k < SEAS; k++) Sr[k] = is[k];
        Sr[SEAS] = is[0];
        L[(size_t)s * N_TIME] = lev;
    }

    CP_WAIT0();
    __syncwarp();

    {   /* scan with stores: lev overwrites consumed y slot, ns -> ts */
        float* myrow = &ty[lane][0] + d;
        float* tsrow = &ts[lane][0];
#pragma unroll
        for (int g = 0; g < TS / SEAS; g++) {
            float yt[SEAS], ax[SEAS];
#pragma unroll
            for (int j = 0; j < SEAS; j++) yt[j] = myrow[g * SEAS + j];
#pragma unroll
            for (int j = 0; j < SEAS; j++) ax[j] = yt[j] * aq[j];
#pragma unroll
            for (int j = 0; j < SEAS; j++) {
                lev = fmaf(oma, lev, ax[j]);
                myrow[g * SEAS + j] = lev;
                float ns = fmaf(omb, ring[j], (b * yt[j]) * frcp(lev));
                tsrow[g * SEAS + j] = ns;
                ring[j] = ns;
                aq[j]   = a * frcp(ns);
            }
        }
    }
    __syncwarp();

    /* coalesced flush: thread = time offset */
    {
        float* Lp = L + (size_t)(sg * 32) * N_TIME + tstart + lane;
        float* Sp = S + (size_t)(sg * 32) * S_LEN + tstart + SEAS + lane;
        const float* typ = &ty[0][0] + d + lane;
        const float* tsp = &ts[0][0] + lane;
#pragma unroll 8
        for (int r = 0; r < 32; r++) {
            Lp[0] = typ[0];
            Sp[0] = tsp[0];
            if (lane < 3) {
                Lp[32] = typ[32];
                Sp[32] = tsp[32];
            }
            Lp += N_TIME; Sp += S_LEN; typ += ROWW; tsp += 37;
        }
    }
}

__global__ void windows_kernel(const float* __restrict__ y,
                               const float* __restrict__ L,
                               const float* __restrict__ S,
                               float* __restrict__ yhat,
                               float* __restrict__ ywin)
{
    const int NH = OUTPUT_SIZE * N_SERIES * INPUT_SIZE;   /* 401408 */
    const int NZ = OUTPUT_SIZE * N_SERIES * OUTPUT_SIZE;  /* 100352 */
    int i = blockIdx.x * blockDim.x + threadIdx.x;
    if (i < NH) {
        int ii   = i % INPUT_SIZE;
        int rest = i / INPUT_SIZE;
        int s    = rest % N_SERIES;
        int w    = rest / N_SERIES;
        int start = N_TIME - INPUT_SIZE - OUTPUT_SIZE + 1 + w;
        int t = start + ii;
        float lev = L[(size_t)s * N_TIME + (start + INPUT_SIZE - 1)];
        float se  = S[(size_t)s * S_LEN  + t];
        float yy  = y[(size_t)s * N_TIME + t];
        yhat[i] = logf(yy / (lev * se));
    } else if (i < NH + NZ) {
        ywin[i - NH] = 0.0f;
    }
}

extern "C" void kernel_launch(void* const* d_in, const int* in_sizes, int n_in,
                              void* d_out, int out_size) {
    const float* y    = (const float*)d_in[0];
    const int*   idxs = (const int*)  d_in[1];
    const float* emb  = (const float*)d_in[2];

    float* out  = (float*)d_out;
    float* yhat = out + OFF_YHAT;
    float* ywin = out + OFF_YWIN;
    float* L    = out + OFF_LEV;
    float* S    = out + OFF_SEAS;

    passA_kernel<<<NCH1 * 32, 32>>>(y, idxs, emb);
    fixup_kernel<<<(N_SERIES + 255) / 256, 256>>>();
    passC_kernel<<<NCH2 * 64, 32>>>(y, idxs, emb, L, S);

    const int tot = OUTPUT_SIZE * N_SERIES * (INPUT_SIZE + OUTPUT_SIZE); /* 501760 */
    windows_kernel<<<(tot + 255) / 256, 256>>>(y, L, S, yhat, ywin);
}